// round 2
// baseline (speedup 1.0000x reference)
#include <cuda_runtime.h>
#include <cuda_bf16.h>

// Depthwise 4x4 FIR upsample x2 (upfirdn2d with k1=[1,3,3,1], factor=2).
// Input  x  : (8, 128, 128, 128) fp32  -> 1024 planes of 128x128
// Output out: (8, 128, 256, 256) fp32  -> 1024 planes of 256x256
//
// Separable weights per dim: even output index 2i  = 0.25*x[i-1] + 0.75*x[i]
//                            odd  output index 2i+1 = 0.75*x[i]  + 0.25*x[i+1]
// (zero padding outside [0,128)).
//
// One thread handles one input row i and 4 input columns [j0, j0+4),
// producing the 2x8 output patch rows {2i, 2i+1}, cols [2*j0, 2*j0+8).

#define IN_H 128
#define IN_W 128
#define OUT_H 256
#define OUT_W 256
#define PLANES 1024

__global__ __launch_bounds__(256, 8)
void up2_fir_kernel(const float* __restrict__ x, float* __restrict__ out) {
    int tid = blockIdx.x * blockDim.x + threadIdx.x;
    // total threads = PLANES * 128 rows * 32 col-groups = 4,194,304
    int j4 = tid & 31;           // column group (4 input cols each)
    int i  = (tid >> 5) & 127;   // input row
    int p  = tid >> 12;          // plane index (b*C + c)

    const float* xp = x + (size_t)p * (IN_H * IN_W);
    const int j0 = j4 * 4;

    // a[c] holds input col (j0 - 1 + c), c = 0..5
    float rm1[6], r0[6], rp1[6];

    const float* row0 = xp + i * IN_W;

    // center row (always valid)
    {
        float4 v = *reinterpret_cast<const float4*>(row0 + j0);
        r0[1] = v.x; r0[2] = v.y; r0[3] = v.z; r0[4] = v.w;
        r0[0] = (j0 > 0)        ? __ldg(row0 + j0 - 1) : 0.0f;
        r0[5] = (j0 + 4 < IN_W) ? __ldg(row0 + j0 + 4) : 0.0f;
    }
    // row above (i-1)
    if (i > 0) {
        const float* rr = row0 - IN_W;
        float4 v = *reinterpret_cast<const float4*>(rr + j0);
        rm1[1] = v.x; rm1[2] = v.y; rm1[3] = v.z; rm1[4] = v.w;
        rm1[0] = (j0 > 0)        ? __ldg(rr + j0 - 1) : 0.0f;
        rm1[5] = (j0 + 4 < IN_W) ? __ldg(rr + j0 + 4) : 0.0f;
    } else {
        #pragma unroll
        for (int c = 0; c < 6; c++) rm1[c] = 0.0f;
    }
    // row below (i+1)
    if (i + 1 < IN_H) {
        const float* rr = row0 + IN_W;
        float4 v = *reinterpret_cast<const float4*>(rr + j0);
        rp1[1] = v.x; rp1[2] = v.y; rp1[3] = v.z; rp1[4] = v.w;
        rp1[0] = (j0 > 0)        ? __ldg(rr + j0 - 1) : 0.0f;
        rp1[5] = (j0 + 4 < IN_W) ? __ldg(rr + j0 + 4) : 0.0f;
    } else {
        #pragma unroll
        for (int c = 0; c < 6; c++) rp1[c] = 0.0f;
    }

    // vertical blend: top = out row 2i, bot = out row 2i+1
    float vt[6], vb[6];
    #pragma unroll
    for (int c = 0; c < 6; c++) {
        vt[c] = fmaf(0.25f, rm1[c], 0.75f * r0[c]);
        vb[c] = fmaf(0.25f, rp1[c], 0.75f * r0[c]);
    }

    // horizontal blend: 8 outputs per row
    float ht[8], hb[8];
    #pragma unroll
    for (int s = 0; s < 4; s++) {
        // even out col 2*(j0+s): 0.25*col(j0+s-1) + 0.75*col(j0+s)
        ht[2*s]   = fmaf(0.25f, vt[s],   0.75f * vt[s+1]);
        hb[2*s]   = fmaf(0.25f, vb[s],   0.75f * vb[s+1]);
        // odd out col 2*(j0+s)+1: 0.75*col(j0+s) + 0.25*col(j0+s+1)
        ht[2*s+1] = fmaf(0.25f, vt[s+2], 0.75f * vt[s+1]);
        hb[2*s+1] = fmaf(0.25f, vb[s+2], 0.75f * vb[s+1]);
    }

    float* op = out + (size_t)p * (OUT_H * OUT_W) + (2 * i) * OUT_W + 2 * j0;
    *reinterpret_cast<float4*>(op)              = make_float4(ht[0], ht[1], ht[2], ht[3]);
    *reinterpret_cast<float4*>(op + 4)          = make_float4(ht[4], ht[5], ht[6], ht[7]);
    *reinterpret_cast<float4*>(op + OUT_W)      = make_float4(hb[0], hb[1], hb[2], hb[3]);
    *reinterpret_cast<float4*>(op + OUT_W + 4)  = make_float4(hb[4], hb[5], hb[6], hb[7]);
}

extern "C" void kernel_launch(void* const* d_in, const int* in_sizes, int n_in,
                              void* d_out, int out_size) {
    const float* x = (const float*)d_in[0];
    float* out = (float*)d_out;
    const int total_threads = PLANES * IN_H * (IN_W / 4);  // 4,194,304
    const int block = 256;
    const int grid = total_threads / block;                // 16,384
    up2_fir_kernel<<<grid, block>>>(x, out);
}

// round 5
// speedup vs baseline: 1.1821x; 1.1821x over previous
#include <cuda_runtime.h>
#include <cuda_bf16.h>

// Depthwise 4x4 FIR upsample x2 (upfirdn2d, k1=[1,3,3,1], factor=2).
// Input  x  : (8, 128, 128, 128) fp32
// Output out: (8, 128, 256, 256) fp32
//
// Separable: even out 2i  = 0.25*x[i-1] + 0.75*x[i]
//            odd  out 2i+1 = 0.75*x[i]  + 0.25*x[i+1]   (zero pad)
//
// One thread = one input row i, 4 input cols [4*lane, 4*lane+4).
// A warp spans one full input row (32 lanes * 4 cols = 128), so horizontal
// halos come from neighbor lanes via warp shuffle — zero L1 traffic.
// Per-warp L1 wavefronts: 3 loads x 4 + 4 stores x 4 = 28 (all mandatory).

#define IN_H 128
#define IN_W 128
#define OUT_H 256
#define OUT_W 256
#define PLANES 1024

__global__ __launch_bounds__(256, 8)
void up2_fir_kernel(const float* __restrict__ x, float* __restrict__ out) {
    int tid = blockIdx.x * blockDim.x + threadIdx.x;
    int lane = tid & 31;         // column group (4 input cols each); warp == row
    int i  = (tid >> 5) & 127;   // input row
    int p  = tid >> 12;          // plane index (b*C + c)

    const float* row0 = x + (size_t)p * (IN_H * IN_W) + i * IN_W;
    const int j0 = lane * 4;

    // a[c] holds input col (j0 - 1 + c), c = 0..5
    float rm1[6], r0[6], rp1[6];

    // center row (always valid)
    {
        float4 v = *reinterpret_cast<const float4*>(row0 + j0);
        r0[1] = v.x; r0[2] = v.y; r0[3] = v.z; r0[4] = v.w;
        r0[0] = __shfl_up_sync(0xffffffffu, v.w, 1);
        r0[5] = __shfl_down_sync(0xffffffffu, v.x, 1);
    }
    // row above (i-1)
    if (i > 0) {
        float4 v = *reinterpret_cast<const float4*>(row0 - IN_W + j0);
        rm1[1] = v.x; rm1[2] = v.y; rm1[3] = v.z; rm1[4] = v.w;
        rm1[0] = __shfl_up_sync(0xffffffffu, v.w, 1);
        rm1[5] = __shfl_down_sync(0xffffffffu, v.x, 1);
    } else {
        #pragma unroll
        for (int c = 0; c < 6; c++) rm1[c] = 0.0f;
    }
    // row below (i+1)
    if (i + 1 < IN_H) {
        float4 v = *reinterpret_cast<const float4*>(row0 + IN_W + j0);
        rp1[1] = v.x; rp1[2] = v.y; rp1[3] = v.z; rp1[4] = v.w;
        rp1[0] = __shfl_up_sync(0xffffffffu, v.w, 1);
        rp1[5] = __shfl_down_sync(0xffffffffu, v.x, 1);
    } else {
        #pragma unroll
        for (int c = 0; c < 6; c++) rp1[c] = 0.0f;
    }

    // image-boundary zeros coincide with warp-edge lanes
    if (lane == 0)  { rm1[0] = 0.0f; r0[0] = 0.0f; rp1[0] = 0.0f; }
    if (lane == 31) { rm1[5] = 0.0f; r0[5] = 0.0f; rp1[5] = 0.0f; }

    // vertical blend: top = out row 2i, bot = out row 2i+1
    float vt[6], vb[6];
    #pragma unroll
    for (int c = 0; c < 6; c++) {
        vt[c] = fmaf(0.25f, rm1[c], 0.75f * r0[c]);
        vb[c] = fmaf(0.25f, rp1[c], 0.75f * r0[c]);
    }

    // horizontal blend: 8 outputs per row
    float ht[8], hb[8];
    #pragma unroll
    for (int s = 0; s < 4; s++) {
        ht[2*s]   = fmaf(0.25f, vt[s],   0.75f * vt[s+1]);
        hb[2*s]   = fmaf(0.25f, vb[s],   0.75f * vb[s+1]);
        ht[2*s+1] = fmaf(0.25f, vt[s+2], 0.75f * vt[s+1]);
        hb[2*s+1] = fmaf(0.25f, vb[s+2], 0.75f * vb[s+1]);
    }

    float* op = out + (size_t)p * (OUT_H * OUT_W) + (2 * i) * OUT_W + 2 * j0;
    *reinterpret_cast<float4*>(op)              = make_float4(ht[0], ht[1], ht[2], ht[3]);
    *reinterpret_cast<float4*>(op + 4)          = make_float4(ht[4], ht[5], ht[6], ht[7]);
    *reinterpret_cast<float4*>(op + OUT_W)      = make_float4(hb[0], hb[1], hb[2], hb[3]);
    *reinterpret_cast<float4*>(op + OUT_W + 4)  = make_float4(hb[4], hb[5], hb[6], hb[7]);
}

extern "C" void kernel_launch(void* const* d_in, const int* in_sizes, int n_in,
                              void* d_out, int out_size) {
    const float* x = (const float*)d_in[0];
    float* out = (float*)d_out;
    const int total_threads = PLANES * IN_H * (IN_W / 4);  // 4,194,304
    const int block = 256;
    const int grid = total_threads / block;                // 16,384
    up2_fir_kernel<<<grid, block>>>(x, out);
}